// round 3
// baseline (speedup 1.0000x reference)
#include <cuda_runtime.h>
#include <cuda_bf16.h>

// ISTFT: B=8192 batch, F=257 bins, T=6 frames, n_fft=512, hop=128, out len 600.
// One CTA per batch element. irfft-512 done as 256-pt complex IFFT via the
// real-FFT half-size decomposition. Fully fused: load -> irfft -> window ->
// overlap-add -> COLA envelope division -> crop.

#define NTHREADS 256

__global__ __launch_bounds__(NTHREADS) void istft_kernel(
    const float* __restrict__ x,   // [B, 1, 257, 6, 2] contiguous
    float* __restrict__ out)       // [B, 1, 600]
{
    const int b   = blockIdx.x;
    const int tid = threadIdx.x;

    __shared__ float  raw[3084];        // one batch element's input (contiguous)
    __shared__ float2 Z[6][256];        // per-frame complex work buffer

    // ---- 1. coalesced staging: 3084 floats = 771 float4 ----
    {
        const float4* src = reinterpret_cast<const float4*>(x + (size_t)b * 3084);
        float4* dst = reinterpret_cast<float4*>(raw);
        #pragma unroll
        for (int i = tid; i < 771; i += NTHREADS) dst[i] = src[i];
    }
    __syncthreads();

    // ---- 2. build Z[k] = E[k] + i*O[k], written bit-reversed ----
    // E[k] = (X[k] + conj(X[256-k]))/2
    // O[k] = (X[k] - conj(X[256-k]))/2 * e^{+2*pi*i*k/512}
    // DC/Nyquist imaginary parts are ignored (irfft semantics).
    #pragma unroll
    for (int item = tid; item < 6 * 256; item += NTHREADS) {
        const int k = item & 255;
        const int t = item >> 8;
        float Xr = raw[k * 12 + t * 2 + 0];
        float Xi = raw[k * 12 + t * 2 + 1];
        const int m = 256 - k;                  // k=0 -> Nyquist bin 256
        float Yr = raw[m * 12 + t * 2 + 0];
        float Yi = raw[m * 12 + t * 2 + 1];
        if (k == 0) { Xi = 0.0f; Yi = 0.0f; }   // drop DC & Nyquist imag

        const float Er = 0.5f * (Xr + Yr);
        const float Ei = 0.5f * (Xi - Yi);
        const float Dr = 0.5f * (Xr - Yr);
        const float Di = 0.5f * (Xi + Yi);

        float s, c;                              // e^{+2*pi*i*k/512} = e^{i*pi*k/256}
        sincospif((float)k * (1.0f / 256.0f), &s, &c);
        const float Or = Dr * c - Di * s;
        const float Oi = Dr * s + Di * c;

        const int kr = __brev((unsigned)k) >> 24;   // 8-bit reversal
        Z[t][kr] = make_float2(Er - Oi, Ei + Or);
    }
    __syncthreads();

    // ---- 3. in-place radix-2 DIT inverse FFT (256 pts x 6 frames) ----
    #pragma unroll
    for (int stage = 1; stage <= 8; stage++) {
        const int len  = 1 << stage;
        const int half = len >> 1;
        #pragma unroll
        for (int item = tid; item < 6 * 128; item += NTHREADS) {
            const int bfly  = item & 127;
            const int t     = item >> 7;
            const int pos   = bfly & (half - 1);
            const int group = bfly >> (stage - 1);
            const int i0    = group * len + pos;
            const int i1    = i0 + half;

            float s, c;                          // e^{+2*pi*i*pos/len}
            sincospif((float)pos * (2.0f / (float)len), &s, &c);

            const float2 u = Z[t][i0];
            const float2 v = Z[t][i1];
            const float vr = v.x * c - v.y * s;
            const float vi = v.x * s + v.y * c;
            Z[t][i0] = make_float2(u.x + vr, u.y + vi);
            Z[t][i1] = make_float2(u.x - vr, u.y - vi);
        }
        __syncthreads();
    }
    // now z[j] = Z[t][j] holds frame samples: frame[2j]=Re z[j], frame[2j+1]=Im z[j]
    // (unnormalized by 1/256; folded into the final scale below)

    // ---- 4. window + overlap-add + COLA envelope + crop ----
    for (int n = tid; n < 600; n += NTHREADS) {
        const int p = n + 256;                  // center=True trim of n_fft/2
        float acc = 0.0f;
        float env = 0.0f;
        #pragma unroll
        for (int t = 0; t < 6; t++) {
            const int j = p - 128 * t;
            if (j >= 0 && j < 512) {
                // hann periodic: 0.5 - 0.5*cos(2*pi*j/512) = 0.5 - 0.5*cos(pi*j/256)
                const float w = 0.5f - 0.5f * cospif((float)j * (1.0f / 256.0f));
                const float2 zz = Z[t][j >> 1];
                const float  v  = (j & 1) ? zz.y : zz.x;
                acc += w * v;
                env += w * w;
            }
        }
        out[(size_t)b * 600 + n] = acc / (256.0f * env);
    }
}

extern "C" void kernel_launch(void* const* d_in, const int* in_sizes, int n_in,
                              void* d_out, int out_size) {
    (void)in_sizes; (void)n_in; (void)out_size;
    const float* x = (const float*)d_in[0];
    float* out = (float*)d_out;
    istft_kernel<<<8192, NTHREADS>>>(x, out);
}

// round 4
// speedup vs baseline: 1.2362x; 1.2362x over previous
#include <cuda_runtime.h>
#include <cuda_bf16.h>

// ISTFT: B=8192, F=257 bins, T=6 frames, n_fft=512, hop=128, out len 600.
// One CTA (192 threads = 6 warps) per batch element; warp w computes frame w.
// irfft-512 = half-size trick -> 256-pt complex inverse FFT done fully in
// registers via the four-step algorithm:
//   N = 256 = N1(32 lanes) x N2(8 register slots), n = n1 + 32*n2
//   1) 8-pt inverse DIT FFT over register slots (per lane)
//   2) twiddle W_256^{+n1*k2}
//   3) 32-pt inverse DIF FFT across lanes via shfl_xor (bit-reversed k1 out,
//      absorbed into the shared-memory store index)
// Shared memory is used only for input staging (transposed per-frame rows)
// and the final frame buffer consumed by overlap-add + COLA division.

#define NT 192

__device__ __forceinline__ void cross_stage(float (&Br)[8], float (&Bi)[8],
                                            int lane, int d) {
    const bool hi = (lane & d) != 0;
    float sn, cs;
    sincospif((float)(lane & (d - 1)) / (float)d, &sn, &cs);  // e^{+i*pi*(l&(d-1))/d}
    if (!hi) { cs = 1.0f; sn = 0.0f; }
    #pragma unroll
    for (int s = 0; s < 8; s++) {
        const float pr = __shfl_xor_sync(0xffffffffu, Br[s], d);
        const float pi = __shfl_xor_sync(0xffffffffu, Bi[s], d);
        const float ar = hi ? (pr - Br[s]) : (Br[s] + pr);
        const float ai = hi ? (pi - Bi[s]) : (Bi[s] + pi);
        Br[s] = ar * cs - ai * sn;
        Bi[s] = ar * sn + ai * cs;
    }
}

__global__ __launch_bounds__(NT) void istft_kernel(
    const float* __restrict__ x,   // [B, 1, 257, 6, 2] contiguous
    float* __restrict__ out)       // [B, 1, 600]
{
    const int b    = blockIdx.x;
    const int tid  = threadIdx.x;
    const int lane = tid & 31;
    const int t    = tid >> 5;     // warp id == frame id (6 warps)

    __shared__ float  rawT[6 * 257 * 2];   // transposed: [frame][bin] complex
    __shared__ float2 Zs[6][288];          // 32 lane-rows * 9 (padded) per frame

    // ---- 1. coalesced gmem read, transposed scatter into per-frame rows ----
    {
        const float4* src = reinterpret_cast<const float4*>(x + (size_t)b * 3084);
        for (int i = tid; i < 771; i += NT) {
            const float4 v = src[i];
            const int idx = 4 * i;
            float comp[4] = {v.x, v.y, v.z, v.w};
            #pragma unroll
            for (int c = 0; c < 4; c++) {
                const int id = idx + c;        // id = k*12 + tt*2 + ri
                const int k  = id / 12;
                const int r  = id - k * 12;
                const int tt = r >> 1;
                rawT[(tt * 257 + k) * 2 + (r & 1)] = comp[c];
            }
        }
    }
    __syncthreads();

    // ---- 2. preprocessing (half-size combine) into registers, slots loaded
    //         in bit-reversed n2 order for the in-register DIT 8-pt FFT ----
    float Br[8], Bi[8];
    const float2* rowT = reinterpret_cast<const float2*>(rawT) + t * 257;
    #pragma unroll
    for (int j = 0; j < 8; j++) {
        const int n2 = ((j & 1) << 2) | (j & 2) | ((j & 4) >> 2);  // brev3(j)
        const int n  = lane + (n2 << 5);          // z index, 0..255
        float2 X = rowT[n];
        float2 Y = rowT[256 - n];
        if (n == 0) { X.y = 0.0f; Y.y = 0.0f; }   // drop DC & Nyquist imag
        const float Er = 0.5f * (X.x + Y.x);
        const float Ei = 0.5f * (X.y - Y.y);
        const float Dr = 0.5f * (X.x - Y.x);
        const float Di = 0.5f * (X.y + Y.y);
        float sn, cs;                              // e^{+i*pi*n/256}
        sincospif((float)n * (1.0f / 256.0f), &sn, &cs);
        const float Or = Dr * cs - Di * sn;
        const float Oi = Dr * sn + Di * cs;
        Br[j] = Er - Oi;
        Bi[j] = Ei + Or;
    }

    // ---- 3a. inner 8-pt inverse DIT FFT over register slots ----
    // stage 1
    #pragma unroll
    for (int q = 0; q < 8; q += 2) {
        const float ur = Br[q], ui = Bi[q], vr = Br[q + 1], vi = Bi[q + 1];
        Br[q] = ur + vr; Bi[q] = ui + vi;
        Br[q + 1] = ur - vr; Bi[q + 1] = ui - vi;
    }
    // stage 2 (twiddles 1, +i)
    #pragma unroll
    for (int g = 0; g < 8; g += 4) {
        { const float ur = Br[g], ui = Bi[g], vr = Br[g + 2], vi = Bi[g + 2];
          Br[g] = ur + vr; Bi[g] = ui + vi;
          Br[g + 2] = ur - vr; Bi[g + 2] = ui - vi; }
        { const float ur = Br[g + 1], ui = Bi[g + 1];
          const float vr = -Bi[g + 3], vi = Br[g + 3];   // i * v
          Br[g + 1] = ur + vr; Bi[g + 1] = ui + vi;
          Br[g + 3] = ur - vr; Bi[g + 3] = ui - vi; }
    }
    // stage 3 (twiddles W8^{0..3} = 1, (R,R), i, (-R,R))
    {
        const float R = 0.70710678118654752440f;
        { const float ur = Br[0], ui = Bi[0], vr = Br[4], vi = Bi[4];
          Br[0] = ur + vr; Bi[0] = ui + vi; Br[4] = ur - vr; Bi[4] = ui - vi; }
        { const float vr0 = Br[5], vi0 = Bi[5];
          const float vr = R * (vr0 - vi0), vi = R * (vr0 + vi0);
          const float ur = Br[1], ui = Bi[1];
          Br[1] = ur + vr; Bi[1] = ui + vi; Br[5] = ur - vr; Bi[5] = ui - vi; }
        { const float vr = -Bi[6], vi = Br[6];
          const float ur = Br[2], ui = Bi[2];
          Br[2] = ur + vr; Bi[2] = ui + vi; Br[6] = ur - vr; Bi[6] = ui - vi; }
        { const float vr0 = Br[7], vi0 = Bi[7];
          const float vr = -R * (vr0 + vi0), vi = R * (vr0 - vi0);
          const float ur = Br[3], ui = Bi[3];
          Br[3] = ur + vr; Bi[3] = ui + vi; Br[7] = ur - vr; Bi[7] = ui - vi; }
    }

    // ---- 3b. four-step twiddle W_256^{+lane*k2} ----
    #pragma unroll
    for (int k2 = 1; k2 < 8; k2++) {
        float sn, cs;
        sincospif((float)(lane * k2) * (1.0f / 128.0f), &sn, &cs);
        const float br = Br[k2] * cs - Bi[k2] * sn;
        Bi[k2] = Br[k2] * sn + Bi[k2] * cs;
        Br[k2] = br;
    }

    // ---- 3c. 32-pt inverse DIF FFT across lanes (bit-reversed output) ----
    cross_stage(Br, Bi, lane, 16);
    cross_stage(Br, Bi, lane, 8);
    cross_stage(Br, Bi, lane, 4);
    cross_stage(Br, Bi, lane, 2);
    cross_stage(Br, Bi, lane, 1);

    // lane l, slot s now holds X[s + 8*brev5(l)]; store at padded physical
    // row l (9 float2 per row) so OLA does the bit-reversal on lookup.
    {
        float2* zrow = &Zs[t][lane * 9];
        #pragma unroll
        for (int s = 0; s < 8; s++) zrow[s] = make_float2(Br[s], Bi[s]);
    }
    __syncthreads();

    // ---- 4. window + overlap-add + COLA envelope + crop ----
    // frame sample f[2j] = Re z[j], f[2j+1] = Im z[j]; 1/256 folded into scale.
    for (int n = tid; n < 600; n += NT) {
        const int p = n + 256;                    // center=True trim
        float acc = 0.0f;
        float env = 0.0f;
        #pragma unroll
        for (int tt = 0; tt < 6; tt++) {
            const int j = p - 128 * tt;
            if (j >= 0 && j < 512) {
                const float w = 0.5f - 0.5f * cospif((float)j * (1.0f / 256.0f));
                const int jz = j >> 1;
                const int phys = (int)(__brev((unsigned)(jz >> 3)) >> 27) * 9 + (jz & 7);
                const float2 zz = Zs[tt][phys];
                const float v = (j & 1) ? zz.y : zz.x;
                acc += w * v;
                env += w * w;
            }
        }
        out[(size_t)b * 600 + n] = acc / (256.0f * env);
    }
}

extern "C" void kernel_launch(void* const* d_in, const int* in_sizes, int n_in,
                              void* d_out, int out_size) {
    (void)in_sizes; (void)n_in; (void)out_size;
    const float* x = (const float*)d_in[0];
    float* out = (float*)d_out;
    istft_kernel<<<8192, NT>>>(x, out);
}

// round 5
// speedup vs baseline: 1.9915x; 1.6110x over previous
#include <cuda_runtime.h>
#include <cuda_bf16.h>

// ISTFT: B=8192, F=257 bins, T=6 frames, n_fft=512, hop=128, out len 600.
// One CTA (192 threads = 6 warps) per batch element; warp w computes frame w.
// irfft-512 = half-size trick -> 256-pt complex inverse FFT fully in registers:
//   8-pt DIT over register slots  x  32-pt DIF across lanes (shfl_xor),
// bit-reversal absorbed into the shared store. Cheap MUFU trig + recurrences
// for all twiddles; Hann window via shared LUT.

#define NT 192
#define PI_F 3.14159265358979323846f

__device__ __forceinline__ void cross_stage(float (&Br)[8], float (&Bi)[8],
                                            int lane, int d) {
    const bool hi = (lane & d) != 0;
    float sn, cs;
    __sincosf((float)(lane & (d - 1)) * (PI_F / (float)d), &sn, &cs);
    if (!hi) { cs = 1.0f; sn = 0.0f; }
    #pragma unroll
    for (int s = 0; s < 8; s++) {
        const float pr = __shfl_xor_sync(0xffffffffu, Br[s], d);
        const float pq = __shfl_xor_sync(0xffffffffu, Bi[s], d);
        const float ar = hi ? (pr - Br[s]) : (Br[s] + pr);
        const float ai = hi ? (pq - Bi[s]) : (Bi[s] + pq);
        Br[s] = ar * cs - ai * sn;
        Bi[s] = ar * sn + ai * cs;
    }
}

__global__ __launch_bounds__(NT) void istft_kernel(
    const float* __restrict__ x,   // [B, 1, 257, 6, 2] contiguous
    float* __restrict__ out)       // [B, 1, 600]
{
    const int b    = blockIdx.x;
    const int tid  = threadIdx.x;
    const int lane = tid & 31;
    const int t    = tid >> 5;     // warp id == frame id

    // pool: first used as rawT [6][257] float2 (1542), then as Zs [6][288]
    __shared__ float2 pool[1728];
    __shared__ float  wtab[512];

    // ---- 0. Hann window LUT (periodic): w(j) = 0.5 - 0.5 cos(pi j/256) ----
    for (int j = tid; j < 512; j += NT)
        wtab[j] = 0.5f - 0.5f * __cosf((float)j * (PI_F / 256.0f));

    // ---- 1. coalesced stage, transposed to [frame][bin] complex ----
    {
        const float4* src = reinterpret_cast<const float4*>(x + (size_t)b * 3084);
        for (int i = tid; i < 771; i += NT) {
            const float4 v = src[i];
            const int q  = i / 3;          // bin index
            const int rr = i - 3 * q;      // frames 2rr, 2rr+1
            pool[(2 * rr)     * 257 + q] = make_float2(v.x, v.y);
            pool[(2 * rr + 1) * 257 + q] = make_float2(v.z, v.w);
        }
    }
    __syncthreads();

    // ---- 2. half-size combine, twiddle recurrence, bit-reversed slots ----
    float Br[8], Bi[8];
    {
        const float2* rowT = pool + t * 257;
        float twc, tws;                         // e^{i*pi*lane/256}
        __sincosf((float)lane * (PI_F / 256.0f), &tws, &twc);
        const float W32c = 0.92387953251128675613f;  // cos(pi/8)
        const float W32s = 0.38268343236508977172f;  // sin(pi/8)
        #pragma unroll
        for (int j = 0; j < 8; j++) {
            const int slot = (((j & 1) << 2) | (j & 2) | (j >> 2));  // brev3(j)
            const int n = lane + (j << 5);
            float2 X = rowT[n];
            float2 Y = rowT[256 - n];
            if (n == 0) { X.y = 0.0f; Y.y = 0.0f; }  // DC & Nyquist imag
            const float Er = 0.5f * (X.x + Y.x);
            const float Ei = 0.5f * (X.y - Y.y);
            const float Dr = 0.5f * (X.x - Y.x);
            const float Di = 0.5f * (X.y + Y.y);
            const float Or = Dr * twc - Di * tws;
            const float Oi = Dr * tws + Di * twc;
            Br[slot] = Er - Oi;
            Bi[slot] = Ei + Or;
            const float nc = twc * W32c - tws * W32s;   // tw *= e^{i*pi/8}
            tws = twc * W32s + tws * W32c;
            twc = nc;
        }
    }

    // ---- 3a. inner 8-pt inverse DIT FFT over register slots ----
    #pragma unroll
    for (int q = 0; q < 8; q += 2) {
        const float ur = Br[q], ui = Bi[q], vr = Br[q + 1], vi = Bi[q + 1];
        Br[q] = ur + vr; Bi[q] = ui + vi;
        Br[q + 1] = ur - vr; Bi[q + 1] = ui - vi;
    }
    #pragma unroll
    for (int g = 0; g < 8; g += 4) {
        { const float ur = Br[g], ui = Bi[g], vr = Br[g + 2], vi = Bi[g + 2];
          Br[g] = ur + vr; Bi[g] = ui + vi;
          Br[g + 2] = ur - vr; Bi[g + 2] = ui - vi; }
        { const float ur = Br[g + 1], ui = Bi[g + 1];
          const float vr = -Bi[g + 3], vi = Br[g + 3];   // i * v
          Br[g + 1] = ur + vr; Bi[g + 1] = ui + vi;
          Br[g + 3] = ur - vr; Bi[g + 3] = ui - vi; }
    }
    {
        const float R = 0.70710678118654752440f;
        { const float ur = Br[0], ui = Bi[0], vr = Br[4], vi = Bi[4];
          Br[0] = ur + vr; Bi[0] = ui + vi; Br[4] = ur - vr; Bi[4] = ui - vi; }
        { const float vr0 = Br[5], vi0 = Bi[5];
          const float vr = R * (vr0 - vi0), vi = R * (vr0 + vi0);
          const float ur = Br[1], ui = Bi[1];
          Br[1] = ur + vr; Bi[1] = ui + vi; Br[5] = ur - vr; Bi[5] = ui - vi; }
        { const float vr = -Bi[6], vi = Br[6];
          const float ur = Br[2], ui = Bi[2];
          Br[2] = ur + vr; Bi[2] = ui + vi; Br[6] = ur - vr; Bi[6] = ui - vi; }
        { const float vr0 = Br[7], vi0 = Bi[7];
          const float vr = -R * (vr0 + vi0), vi = R * (vr0 - vi0);
          const float ur = Br[3], ui = Bi[3];
          Br[3] = ur + vr; Bi[3] = ui + vi; Br[7] = ur - vr; Bi[7] = ui - vi; }
    }

    // ---- 3b. four-step twiddle W_256^{+lane*k2} via recurrence ----
    {
        float wc, ws;                           // e^{i*pi*lane/128}
        __sincosf((float)lane * (PI_F / 128.0f), &ws, &wc);
        float cc = wc, cs = ws;
        #pragma unroll
        for (int k2 = 1; k2 < 8; k2++) {
            const float br = Br[k2] * cc - Bi[k2] * cs;
            Bi[k2] = Br[k2] * cs + Bi[k2] * cc;
            Br[k2] = br;
            const float nc = cc * wc - cs * ws;
            cs = cc * ws + cs * wc;
            cc = nc;
        }
    }

    // ---- 3c. 32-pt inverse DIF FFT across lanes ----
    cross_stage(Br, Bi, lane, 16);
    cross_stage(Br, Bi, lane, 8);
    cross_stage(Br, Bi, lane, 4);
    cross_stage(Br, Bi, lane, 2);
    cross_stage(Br, Bi, lane, 1);

    // ---- 3d. unscrambled store: lane holds X[s + 8*brev5(lane)] ----
    __syncthreads();   // rawT fully consumed before pool is overwritten as Zs
    {
        const int chunk = (int)(__brev((unsigned)lane) >> 27);
        float2* zrow = pool + t * 288 + chunk * 9;   // padded rows: 2-way max
        #pragma unroll
        for (int s = 0; s < 8; s++) zrow[s] = make_float2(Br[s], Bi[s]);
    }
    __syncthreads();

    // ---- 4. window + overlap-add + COLA envelope + crop ----
    const float* poolf = reinterpret_cast<const float*>(pool);
    for (int n = tid; n < 600; n += NT) {
        const int p   = n + 256;               // center=True trim
        const int odd = p & 1;                 // parity fixed across frames
        float acc = 0.0f, env = 0.0f;
        #pragma unroll
        for (int tt = 0; tt < 6; tt++) {
            const int j = p - 128 * tt;
            if (j >= 0 && j < 512) {
                const float w  = wtab[j];
                const int jz   = j >> 1;
                const int phys = (jz >> 3) * 9 + (jz & 7);
                const float v  = poolf[(tt * 288 + phys) * 2 + odd];
                acc = fmaf(w, v, acc);
                env = fmaf(w, w, env);
            }
        }
        out[(size_t)b * 600 + n] = __fdividef(acc, 256.0f * env);
    }
}

extern "C" void kernel_launch(void* const* d_in, const int* in_sizes, int n_in,
                              void* d_out, int out_size) {
    (void)in_sizes; (void)n_in; (void)out_size;
    const float* x = (const float*)d_in[0];
    float* out = (float*)d_out;
    istft_kernel<<<8192, NT>>>(x, out);
}

// round 6
// speedup vs baseline: 2.1933x; 1.1013x over previous
#include <cuda_runtime.h>
#include <cuda_bf16.h>

// ISTFT: B=8192, F=257 bins, T=6 frames, n_fft=512, hop=128, out len 600.
// One CTA (192 threads = 6 warps) per batch element; warp w computes frame w.
// irfft-512 = half-size trick -> 256-pt complex inverse FFT fully in registers:
//   8-pt DIT over register slots  x  32-pt DIF across lanes (shfl_xor),
// bit-reversal absorbed into the shared store. All twiddles via MUFU trig +
// recurrences. OLA windows computed analytically from ONE __sincosf per
// output sample (cos(pi(r+128k)/256) = {c,-s,-c,s}) -- no window LUT.

#define NT 192
#define PI_F 3.14159265358979323846f

__device__ __forceinline__ void cross_stage(float (&Br)[8], float (&Bi)[8],
                                            int lane, int d) {
    const bool hi = (lane & d) != 0;
    float sn, cs;
    __sincosf((float)(lane & (d - 1)) * (PI_F / (float)d), &sn, &cs);
    if (!hi) { cs = 1.0f; sn = 0.0f; }
    #pragma unroll
    for (int s = 0; s < 8; s++) {
        const float pr = __shfl_xor_sync(0xffffffffu, Br[s], d);
        const float pq = __shfl_xor_sync(0xffffffffu, Bi[s], d);
        const float ar = hi ? (pr - Br[s]) : (Br[s] + pr);
        const float ai = hi ? (pq - Bi[s]) : (Bi[s] + pq);
        Br[s] = ar * cs - ai * sn;
        Bi[s] = ar * sn + ai * cs;
    }
}

__global__ __launch_bounds__(NT) void istft_kernel(
    const float* __restrict__ x,   // [B, 1, 257, 6, 2] contiguous
    float* __restrict__ out)       // [B, 1, 600]
{
    const int b    = blockIdx.x;
    const int tid  = threadIdx.x;
    const int lane = tid & 31;
    const int t    = tid >> 5;     // warp id == frame id

    // pool: first rawT [6][258] float2 (1548 used), then Zs [6][288] (1728)
    __shared__ float2 pool[1728];

    // ---- 1. coalesced stage, transposed to [frame][bin] complex ----
    // row stride 258 float2 => row bank offsets {0,4,8,12,16,20}: conflict-free
    {
        const float4* src = reinterpret_cast<const float4*>(x + (size_t)b * 3084);
        for (int i = tid; i < 771; i += NT) {
            const float4 v = src[i];
            const int k  = i / 3;          // bin index
            const int rr = i - 3 * k;      // frame pair 2rr, 2rr+1
            pool[(2 * rr)     * 258 + k] = make_float2(v.x, v.y);
            pool[(2 * rr + 1) * 258 + k] = make_float2(v.z, v.w);
        }
    }
    __syncthreads();

    // ---- 2. half-size combine, twiddle recurrence, bit-reversed slots ----
    float Br[8], Bi[8];
    {
        const float2* rowT = pool + t * 258;
        float twc, tws;                         // e^{i*pi*lane/256}
        __sincosf((float)lane * (PI_F / 256.0f), &tws, &twc);
        const float W32c = 0.92387953251128675613f;  // cos(pi/8)
        const float W32s = 0.38268343236508977172f;  // sin(pi/8)
        #pragma unroll
        for (int j = 0; j < 8; j++) {
            const int slot = (((j & 1) << 2) | (j & 2) | (j >> 2));  // brev3(j)
            const int n = lane + (j << 5);
            float2 X = rowT[n];
            float2 Y = rowT[256 - n];
            if (n == 0) { X.y = 0.0f; Y.y = 0.0f; }  // DC & Nyquist imag
            const float Er = 0.5f * (X.x + Y.x);
            const float Ei = 0.5f * (X.y - Y.y);
            const float Dr = 0.5f * (X.x - Y.x);
            const float Di = 0.5f * (X.y + Y.y);
            const float Or = Dr * twc - Di * tws;
            const float Oi = Dr * tws + Di * twc;
            Br[slot] = Er - Oi;
            Bi[slot] = Ei + Or;
            const float nc = twc * W32c - tws * W32s;   // tw *= e^{i*pi/8}
            tws = twc * W32s + tws * W32c;
            twc = nc;
        }
    }

    // ---- 3a. inner 8-pt inverse DIT FFT over register slots ----
    #pragma unroll
    for (int q = 0; q < 8; q += 2) {
        const float ur = Br[q], ui = Bi[q], vr = Br[q + 1], vi = Bi[q + 1];
        Br[q] = ur + vr; Bi[q] = ui + vi;
        Br[q + 1] = ur - vr; Bi[q + 1] = ui - vi;
    }
    #pragma unroll
    for (int g = 0; g < 8; g += 4) {
        { const float ur = Br[g], ui = Bi[g], vr = Br[g + 2], vi = Bi[g + 2];
          Br[g] = ur + vr; Bi[g] = ui + vi;
          Br[g + 2] = ur - vr; Bi[g + 2] = ui - vi; }
        { const float ur = Br[g + 1], ui = Bi[g + 1];
          const float vr = -Bi[g + 3], vi = Br[g + 3];   // i * v
          Br[g + 1] = ur + vr; Bi[g + 1] = ui + vi;
          Br[g + 3] = ur - vr; Bi[g + 3] = ui - vi; }
    }
    {
        const float R = 0.70710678118654752440f;
        { const float ur = Br[0], ui = Bi[0], vr = Br[4], vi = Bi[4];
          Br[0] = ur + vr; Bi[0] = ui + vi; Br[4] = ur - vr; Bi[4] = ui - vi; }
        { const float vr0 = Br[5], vi0 = Bi[5];
          const float vr = R * (vr0 - vi0), vi = R * (vr0 + vi0);
          const float ur = Br[1], ui = Bi[1];
          Br[1] = ur + vr; Bi[1] = ui + vi; Br[5] = ur - vr; Bi[5] = ui - vi; }
        { const float vr = -Bi[6], vi = Br[6];
          const float ur = Br[2], ui = Bi[2];
          Br[2] = ur + vr; Bi[2] = ui + vi; Br[6] = ur - vr; Bi[6] = ui - vi; }
        { const float vr0 = Br[7], vi0 = Bi[7];
          const float vr = -R * (vr0 + vi0), vi = R * (vr0 - vi0);
          const float ur = Br[3], ui = Bi[3];
          Br[3] = ur + vr; Bi[3] = ui + vi; Br[7] = ur - vr; Bi[7] = ui - vi; }
    }

    // ---- 3b. four-step twiddle W_256^{+lane*k2} via recurrence ----
    {
        float wc, ws;                           // e^{i*pi*lane/128}
        __sincosf((float)lane * (PI_F / 128.0f), &ws, &wc);
        float cc = wc, cs = ws;
        #pragma unroll
        for (int k2 = 1; k2 < 8; k2++) {
            const float br = Br[k2] * cc - Bi[k2] * cs;
            Bi[k2] = Br[k2] * cs + Bi[k2] * cc;
            Br[k2] = br;
            const float nc = cc * wc - cs * ws;
            cs = cc * ws + cs * wc;
            cc = nc;
        }
    }

    // ---- 3c. 32-pt inverse DIF FFT across lanes ----
    cross_stage(Br, Bi, lane, 16);
    cross_stage(Br, Bi, lane, 8);
    cross_stage(Br, Bi, lane, 4);
    cross_stage(Br, Bi, lane, 2);
    cross_stage(Br, Bi, lane, 1);

    // ---- 3d. unscrambled store: lane holds X[s + 8*brev5(lane)] ----
    __syncthreads();   // rawT fully consumed before pool is reused as Zs
    {
        const int chunk = (int)(__brev((unsigned)lane) >> 27);
        float2* zrow = pool + t * 288 + chunk * 9;   // padded rows
        #pragma unroll
        for (int s = 0; s < 8; s++) zrow[s] = make_float2(Br[s], Bi[s]);
    }
    __syncthreads();

    // ---- 4. window + overlap-add + COLA envelope + crop ----
    // p = 128q + r; frame t=q-k contributes sample j=r+128k (k=0..3).
    // cos(pi(r+128k)/256) = {c,-s,-c,s} -> all 4 Hann weights from 1 sincosf.
    // Shared float index is linear in k: A - 432k. k=1,2 always valid;
    // k=0 valid iff q<=5, k=3 valid iff q>=3.
    const float* poolf = reinterpret_cast<const float*>(pool);
    for (int n = tid; n < 600; n += NT) {
        const int p = n + 256;                 // center=True trim
        const int q = p >> 7;                  // 2..6
        const int r = p & 127;
        float s, c;
        __sincosf((float)r * (PI_F / 256.0f), &s, &c);
        const float w0 = 0.5f - 0.5f * c;
        const float w1 = 0.5f + 0.5f * s;
        const float w2 = 0.5f + 0.5f * c;
        const float w3 = 0.5f - 0.5f * s;
        const int rz = r >> 1;
        const int A = (q * 288 + (rz >> 3) * 9 + (rz & 7)) * 2 + (r & 1);

        float acc = w1 * poolf[A - 432] + w2 * poolf[A - 864];
        float env = w1 * w1 + w2 * w2;
        if (q <= 5) { acc = fmaf(w0, poolf[A], acc);        env = fmaf(w0, w0, env); }
        if (q >= 3) { acc = fmaf(w3, poolf[A - 1296], acc); env = fmaf(w3, w3, env); }
        out[(size_t)b * 600 + n] = __fdividef(acc, 256.0f * env);
    }
}

extern "C" void kernel_launch(void* const* d_in, const int* in_sizes, int n_in,
                              void* d_out, int out_size) {
    (void)in_sizes; (void)n_in; (void)out_size;
    const float* x = (const float*)d_in[0];
    float* out = (float*)d_out;
    istft_kernel<<<8192, NT>>>(x, out);
}

// round 7
// speedup vs baseline: 2.5548x; 1.1648x over previous
#include <cuda_runtime.h>
#include <cuda_bf16.h>

// ISTFT: B=8192, F=257 bins, T=6 frames, n_fft=512, hop=128, out len 600.
// One CTA (192 threads = 6 warps) per batch element; warp w computes frame w.
// irfft-512 = half-size trick folded into staging via Hermitian symmetry:
// from bin pair (k,256-k): Z[k]=E+iO and Z[256-k]=conj(E-iO).
// 256-pt complex inverse FFT in registers: 8-pt DIT over slots x 32-pt DIF
// across lanes (shfl_xor), bit-reversal absorbed into addressing.
// OLA handles output pairs, windows from one sincosf + angle addition.

#define NT 192
#define PI_F 3.14159265358979323846f

__device__ __forceinline__ void cross_stage(float (&Br)[8], float (&Bi)[8],
                                            int lane, int d) {
    const bool hi = (lane & d) != 0;
    float sn, cs;
    __sincosf((float)(lane & (d - 1)) * (PI_F / (float)d), &sn, &cs);
    if (!hi) { cs = 1.0f; sn = 0.0f; }
    #pragma unroll
    for (int s = 0; s < 8; s++) {
        const float pr = __shfl_xor_sync(0xffffffffu, Br[s], d);
        const float pq = __shfl_xor_sync(0xffffffffu, Bi[s], d);
        const float ar = hi ? (pr - Br[s]) : (Br[s] + pr);
        const float ai = hi ? (pq - Bi[s]) : (Bi[s] + pq);
        Br[s] = ar * cs - ai * sn;
        Bi[s] = ar * sn + ai * cs;
    }
}

__global__ __launch_bounds__(NT) void istft_kernel(
    const float* __restrict__ x,   // [B, 1, 257, 6, 2] contiguous
    float* __restrict__ out)       // [B, 1, 600]
{
    const int b    = blockIdx.x;
    const int tid  = threadIdx.x;
    const int lane = tid & 31;
    const int t    = tid >> 5;     // warp id == frame id

    // pool: first Z rows [6][258] float2 (1548 used), then frame buf [6][320]
    __shared__ __align__(16) float2 pool[1920];

    // ---- 1. staging + half-size combine (Hermitian pair trick) ----
    // item i<381: bin pair (k=i/3+1, 256-k), rr = frame pair index (0..2)
    // i 381..383: k=0 (with Nyquist bin 256); i 384..386: k=128 self-paired.
    {
        const float4* src = reinterpret_cast<const float4*>(x + (size_t)b * 3084);
        for (int i = tid; i < 387; i += NT) {
            if (i < 381) {
                const int k  = i / 3 + 1;          // 1..127
                const int rr = i - (k - 1) * 3;
                const float4 A  = src[k * 3 + rr];
                const float4 Bv = src[(256 - k) * 3 + rr];
                float s, c;                         // e^{i*pi*k/256}
                __sincosf((float)k * (PI_F / 256.0f), &s, &c);
                #pragma unroll
                for (int f = 0; f < 2; f++) {
                    const float Xr = f ? A.z : A.x,  Xi = f ? A.w : A.y;
                    const float Yr = f ? Bv.z : Bv.x, Yi = f ? Bv.w : Bv.y;
                    const float Er = 0.5f * (Xr + Yr), Ei = 0.5f * (Xi - Yi);
                    const float Dr = 0.5f * (Xr - Yr), Di = 0.5f * (Xi + Yi);
                    const float Or = Dr * c - Di * s;
                    const float Oi = Dr * s + Di * c;
                    const int tt = 2 * rr + f;
                    pool[tt * 258 + k]       = make_float2(Er - Oi, Ei + Or);
                    pool[tt * 258 + 256 - k] = make_float2(Er + Oi, Or - Ei);
                }
            } else if (i < 384) {
                const int rr = i - 381;
                const float4 A  = src[rr];              // bin 0
                const float4 Bv = src[256 * 3 + rr];    // bin 256 (Nyquist)
                pool[(2 * rr)     * 258] = make_float2(0.5f * (A.x + Bv.x), 0.5f * (A.x - Bv.x));
                pool[(2 * rr + 1) * 258] = make_float2(0.5f * (A.z + Bv.z), 0.5f * (A.z - Bv.z));
            } else {
                const int rr = i - 384;
                const float4 A = src[128 * 3 + rr];     // bin 128 (self-pair)
                pool[(2 * rr)     * 258 + 128] = make_float2(A.x, -A.y);
                pool[(2 * rr + 1) * 258 + 128] = make_float2(A.z, -A.w);
            }
        }
    }
    __syncthreads();

    // ---- 2. load Z[lane+32j] into bit-reversed register slots ----
    float Br[8], Bi[8];
    {
        const float2* rowT = pool + t * 258;
        #pragma unroll
        for (int j = 0; j < 8; j++) {
            const int slot = ((j & 1) << 2) | (j & 2) | (j >> 2);  // brev3(j)
            const float2 z = rowT[lane + (j << 5)];
            Br[slot] = z.x;
            Bi[slot] = z.y;
        }
    }

    // ---- 3a. inner 8-pt inverse DIT FFT over register slots ----
    #pragma unroll
    for (int q = 0; q < 8; q += 2) {
        const float ur = Br[q], ui = Bi[q], vr = Br[q + 1], vi = Bi[q + 1];
        Br[q] = ur + vr; Bi[q] = ui + vi;
        Br[q + 1] = ur - vr; Bi[q + 1] = ui - vi;
    }
    #pragma unroll
    for (int g = 0; g < 8; g += 4) {
        { const float ur = Br[g], ui = Bi[g], vr = Br[g + 2], vi = Bi[g + 2];
          Br[g] = ur + vr; Bi[g] = ui + vi;
          Br[g + 2] = ur - vr; Bi[g + 2] = ui - vi; }
        { const float ur = Br[g + 1], ui = Bi[g + 1];
          const float vr = -Bi[g + 3], vi = Br[g + 3];   // i * v
          Br[g + 1] = ur + vr; Bi[g + 1] = ui + vi;
          Br[g + 3] = ur - vr; Bi[g + 3] = ui - vi; }
    }
    {
        const float R = 0.70710678118654752440f;
        { const float ur = Br[0], ui = Bi[0], vr = Br[4], vi = Bi[4];
          Br[0] = ur + vr; Bi[0] = ui + vi; Br[4] = ur - vr; Bi[4] = ui - vi; }
        { const float vr0 = Br[5], vi0 = Bi[5];
          const float vr = R * (vr0 - vi0), vi = R * (vr0 + vi0);
          const float ur = Br[1], ui = Bi[1];
          Br[1] = ur + vr; Bi[1] = ui + vi; Br[5] = ur - vr; Bi[5] = ui - vi; }
        { const float vr = -Bi[6], vi = Br[6];
          const float ur = Br[2], ui = Bi[2];
          Br[2] = ur + vr; Bi[2] = ui + vi; Br[6] = ur - vr; Bi[6] = ui - vi; }
        { const float vr0 = Br[7], vi0 = Bi[7];
          const float vr = -R * (vr0 + vi0), vi = R * (vr0 - vi0);
          const float ur = Br[3], ui = Bi[3];
          Br[3] = ur + vr; Bi[3] = ui + vi; Br[7] = ur - vr; Bi[7] = ui - vi; }
    }

    // ---- 3b. four-step twiddle W_256^{+lane*k2} via recurrence ----
    {
        float wc, ws;                           // e^{i*pi*lane/128}
        __sincosf((float)lane * (PI_F / 128.0f), &ws, &wc);
        float cc = wc, cs = ws;
        #pragma unroll
        for (int k2 = 1; k2 < 8; k2++) {
            const float br = Br[k2] * cc - Bi[k2] * cs;
            Bi[k2] = Br[k2] * cs + Bi[k2] * cc;
            Br[k2] = br;
            const float nc = cc * wc - cs * ws;
            cs = cc * ws + cs * wc;
            cc = nc;
        }
    }

    // ---- 3c. 32-pt inverse DIF FFT across lanes ----
    cross_stage(Br, Bi, lane, 16);
    cross_stage(Br, Bi, lane, 8);
    cross_stage(Br, Bi, lane, 4);
    cross_stage(Br, Bi, lane, 2);
    cross_stage(Br, Bi, lane, 1);

    // ---- 3d. vectorized store: lane holds X[s + 8*brev5(lane)] ----
    __syncthreads();   // Z rows fully consumed before pool reuse
    {
        const int chunk = (int)(__brev((unsigned)lane) >> 27);
        float4* zrow = reinterpret_cast<float4*>(pool + t * 320 + chunk * 10);
        zrow[0] = make_float4(Br[0], Bi[0], Br[1], Bi[1]);
        zrow[1] = make_float4(Br[2], Bi[2], Br[3], Bi[3]);
        zrow[2] = make_float4(Br[4], Bi[4], Br[5], Bi[5]);
        zrow[3] = make_float4(Br[6], Bi[6], Br[7], Bi[7]);
    }
    __syncthreads();

    // ---- 4. paired OLA: outputs (2m, 2m+1) share one float2 per frame ----
    // p = 128q + r (r even); frame q-k contributes float2 at A0 - 480k.
    // cos(pi(r+128k)/256) = {c,-s,-c,s}; odd sample via angle addition.
    const float* poolf = reinterpret_cast<const float*>(pool);
    const float cd = 0.99992470183914454093f;   // cos(pi/256)
    const float sd = 0.01227153828571992608f;   // sin(pi/256)
    for (int m = tid; m < 300; m += NT) {
        const int p = 2 * m + 256;
        const int q = p >> 7;                   // 2..6
        const int r = p & 127;                  // even
        float s, c;
        __sincosf((float)r * (PI_F / 256.0f), &s, &c);
        const float c1 = c * cd - s * sd;       // cos for r+1
        const float s1 = s * cd + c * sd;       // sin for r+1
        const float w0 = 0.5f - 0.5f * c,  u0 = 0.5f - 0.5f * c1;
        const float w1 = 0.5f + 0.5f * s,  u1 = 0.5f + 0.5f * s1;
        const float w2 = 0.5f + 0.5f * c,  u2 = 0.5f + 0.5f * c1;
        const float w3 = 0.5f - 0.5f * s,  u3 = 0.5f - 0.5f * s1;
        const int rz = r >> 1;
        const int A0 = (q * 320 + (rz >> 3) * 10 + (rz & 7)) * 2;

        const float2 v1 = *reinterpret_cast<const float2*>(poolf + A0 - 480);
        const float2 v2 = *reinterpret_cast<const float2*>(poolf + A0 - 960);
        float acc0 = w1 * v1.x + w2 * v2.x;
        float acc1 = u1 * v1.y + u2 * v2.y;
        float env0 = w1 * w1 + w2 * w2;
        float env1 = u1 * u1 + u2 * u2;
        if (q <= 5) {
            const float2 v0 = *reinterpret_cast<const float2*>(poolf + A0);
            acc0 = fmaf(w0, v0.x, acc0); env0 = fmaf(w0, w0, env0);
            acc1 = fmaf(u0, v0.y, acc1); env1 = fmaf(u0, u0, env1);
        }
        if (q >= 3) {
            const float2 v3 = *reinterpret_cast<const float2*>(poolf + A0 - 1440);
            acc0 = fmaf(w3, v3.x, acc0); env0 = fmaf(w3, w3, env0);
            acc1 = fmaf(u3, v3.y, acc1); env1 = fmaf(u3, u3, env1);
        }
        float2 o;
        o.x = __fdividef(acc0, 256.0f * env0);
        o.y = __fdividef(acc1, 256.0f * env1);
        *reinterpret_cast<float2*>(out + (size_t)b * 600 + 2 * m) = o;
    }
}

extern "C" void kernel_launch(void* const* d_in, const int* in_sizes, int n_in,
                              void* d_out, int out_size) {
    (void)in_sizes; (void)n_in; (void)out_size;
    const float* x = (const float*)d_in[0];
    float* out = (float*)d_out;
    istft_kernel<<<8192, NT>>>(x, out);
}

// round 8
// speedup vs baseline: 2.9137x; 1.1405x over previous
#include <cuda_runtime.h>
#include <cuda_bf16.h>

// ISTFT: B=8192, F=257 bins, T=6 frames, n_fft=512, hop=128, out len 600.
// CTA = 192 threads handles TWO batch elements (grid 4096). Each warp owns
// two frames (16 lanes each). irfft-512 = Hermitian half-size trick folded
// into staging -> 256-pt complex inverse FFT via four-step 16x16:
//   16-pt register IFFT (const twiddles) -> e^{i pi L k1/128} twiddle ->
//   16x16 transpose through shared (pitch 17) -> 16-pt register IFFT.
// No cross-lane shuffles at all. OLA on output pairs with analytic windows.

#define NT 192
#define PI_F 3.14159265358979323846f

#define BFLY0(i0,i1) { const float tr=Br[i1], ti=Bi[i1]; \
    Br[i1]=Br[i0]-tr; Bi[i1]=Bi[i0]-ti; Br[i0]+=tr; Bi[i0]+=ti; }
#define BFLYI(i0,i1) { const float tr=-Bi[i1], ti=Br[i1]; \
    Br[i1]=Br[i0]-tr; Bi[i1]=Bi[i0]-ti; Br[i0]+=tr; Bi[i0]+=ti; }
#define BFLYW(i0,i1,cr,ci) { \
    const float vr=Br[i1]*(cr)-Bi[i1]*(ci); \
    const float vi=Br[i1]*(ci)+Bi[i1]*(cr); \
    Br[i1]=Br[i0]-vr; Bi[i1]=Bi[i0]-vi; Br[i0]+=vr; Bi[i0]+=vi; }

// 16-pt inverse DIT FFT (input in bit-reversed slots, output natural order).
__device__ __forceinline__ void ifft16(float (&Br)[16], float (&Bi)[16]) {
    const float R  = 0.70710678118654752440f;   // cos(pi/4)
    const float C8 = 0.92387953251128675613f;   // cos(pi/8)
    const float S8 = 0.38268343236508977172f;   // sin(pi/8)
    BFLY0(0,1)  BFLY0(2,3)   BFLY0(4,5)  BFLY0(6,7)
    BFLY0(8,9)  BFLY0(10,11) BFLY0(12,13) BFLY0(14,15)
    BFLY0(0,2)  BFLYI(1,3)   BFLY0(4,6)  BFLYI(5,7)
    BFLY0(8,10) BFLYI(9,11)  BFLY0(12,14) BFLYI(13,15)
    BFLY0(0,4)  BFLYW(1,5,R,R)   BFLYI(2,6)  BFLYW(3,7,-R,R)
    BFLY0(8,12) BFLYW(9,13,R,R)  BFLYI(10,14) BFLYW(11,15,-R,R)
    BFLY0(0,8)  BFLYW(1,9,C8,S8) BFLYW(2,10,R,R) BFLYW(3,11,S8,C8)
    BFLYI(4,12) BFLYW(5,13,-S8,C8) BFLYW(6,14,-R,R) BFLYW(7,15,-C8,S8)
}

__device__ __forceinline__ int brev4(int v) {
    return ((v & 1) << 3) | ((v & 2) << 1) | ((v & 4) >> 1) | (v >> 3);
}

__global__ __launch_bounds__(NT) void istft_kernel(
    const float* __restrict__ x,   // [B, 1, 257, 6, 2] contiguous
    float* __restrict__ out)       // [B, 1, 600]
{
    const int b2   = blockIdx.x;   // batch-element pair
    const int tid  = threadIdx.x;
    const int lane = tid & 31;
    const int w    = tid >> 5;
    const int sub  = lane >> 4;    // frame-in-warp
    const int L    = lane & 15;
    const int fg   = 2 * w + sub;  // 0..11: global frame; elem = fg/6, t = fg%6

    // pool time-shared: Z [2][6][258] (3096) -> scratch [12][272] (3264)
    //                   -> fbuf [12][256] (3072)
    __shared__ __align__(16) float2 pool[3264];

    // ---- phase 1: staging + Hermitian half-size combine ----
    // Z[k]=E+iO, Z[256-k]=conj(E-iO) from bin pair (k, 256-k).
    {
        for (int i = tid; i < 774; i += NT) {
            const int e  = (i >= 387);
            const int ii = i - 387 * e;
            const float4* src = reinterpret_cast<const float4*>(
                x + ((size_t)b2 * 2 + e) * 3084);
            float2* Zb = pool + e * 1548;
            if (ii < 381) {
                const int k  = ii / 3 + 1;          // 1..127
                const int rr = ii - (k - 1) * 3;
                const float4 A  = src[k * 3 + rr];
                const float4 Bv = src[(256 - k) * 3 + rr];
                float s, c;                          // e^{i*pi*k/256}
                __sincosf((float)k * (PI_F / 256.0f), &s, &c);
                #pragma unroll
                for (int f = 0; f < 2; f++) {
                    const float Xr = f ? A.z : A.x,   Xi = f ? A.w : A.y;
                    const float Yr = f ? Bv.z : Bv.x, Yi = f ? Bv.w : Bv.y;
                    const float Er = 0.5f * (Xr + Yr), Ei = 0.5f * (Xi - Yi);
                    const float Dr = 0.5f * (Xr - Yr), Di = 0.5f * (Xi + Yi);
                    const float Or = Dr * c - Di * s;
                    const float Oi = Dr * s + Di * c;
                    const int tt = 2 * rr + f;
                    Zb[tt * 258 + k]       = make_float2(Er - Oi, Ei + Or);
                    Zb[tt * 258 + 256 - k] = make_float2(Er + Oi, Or - Ei);
                }
            } else if (ii < 384) {
                const int rr = ii - 381;
                const float4 A  = src[rr];               // bin 0
                const float4 Bv = src[256 * 3 + rr];     // bin 256 (Nyquist)
                Zb[(2 * rr)     * 258] = make_float2(0.5f * (A.x + Bv.x), 0.5f * (A.x - Bv.x));
                Zb[(2 * rr + 1) * 258] = make_float2(0.5f * (A.z + Bv.z), 0.5f * (A.z - Bv.z));
            } else {
                const int rr = ii - 384;
                const float4 A = src[128 * 3 + rr];      // bin 128 self-paired
                Zb[(2 * rr)     * 258 + 128] = make_float2(A.x, -A.y);
                Zb[(2 * rr + 1) * 258 + 128] = make_float2(A.z, -A.w);
            }
        }
    }
    __syncthreads();

    // ---- phase 2: load Z[L + 16*n2] into bit-reversed slots ----
    float Br[16], Bi[16];
    {
        const int e = fg >= 6 ? 1 : 0;
        const float2* rowZ = pool + e * 1548 + (fg - 6 * e) * 258;
        #pragma unroll
        for (int s = 0; s < 16; s++) {
            const float2 z = rowZ[L + (brev4(s) << 4)];
            Br[s] = z.x; Bi[s] = z.y;
        }
    }
    __syncthreads();               // Z dead -> pool reusable as scratch

    // ---- inner 16-pt IFFT over n2 (k1 output, natural order) ----
    ifft16(Br, Bi);

    // ---- four-step twiddle e^{+i*pi*L*k1/128} via recurrence ----
    {
        float wc, ws;
        __sincosf((float)L * (PI_F / 128.0f), &ws, &wc);
        float cc = wc, cs = ws;
        #pragma unroll
        for (int k1 = 1; k1 < 16; k1++) {
            const float br = Br[k1] * cc - Bi[k1] * cs;
            Bi[k1] = Br[k1] * cs + Bi[k1] * cc;
            Br[k1] = br;
            const float nc = cc * wc - cs * ws;
            cs = cc * ws + cs * wc;
            cc = nc;
        }
    }

    // ---- 16x16 transpose through shared (pitch 17, conflict-free) ----
    {
        float2* scr = pool + fg * 272;
        #pragma unroll
        for (int k1 = 0; k1 < 16; k1++)
            scr[L * 17 + k1] = make_float2(Br[k1], Bi[k1]);
        __syncwarp();
        #pragma unroll
        for (int s = 0; s < 16; s++) {
            const float2 z = scr[brev4(s) * 17 + L];   // row n1, column k1=L
            Br[s] = z.x; Bi[s] = z.y;
        }
    }
    __syncthreads();               // scratch dead -> pool reusable as fbuf

    // ---- outer 16-pt IFFT over n1: slot k2 = X[L + 16*k2] ----
    ifft16(Br, Bi);

    // ---- store frame buffer (natural order) ----
    {
        float2* fb = pool + fg * 256;
        #pragma unroll
        for (int k2 = 0; k2 < 16; k2++)
            fb[L + (k2 << 4)] = make_float2(Br[k2], Bi[k2]);
    }
    __syncthreads();

    // ---- paired OLA: outputs (2m, 2m+1) share one float2 per frame ----
    // p = 128q + r (r even); frame q-k at float2 index base - 192k.
    // cos(pi(r+128k)/256) = {c,-s,-c,s}; odd-sample window by angle addition.
    const float2* fb = pool;
    const float cd = 0.99992470183914454093f;   // cos(pi/256)
    const float sd = 0.01227153828571992608f;   // sin(pi/256)
    for (int mm = tid; mm < 600; mm += NT) {
        const int e = (mm >= 300);
        const int m = mm - 300 * e;
        const int p = 2 * m + 256;
        const int q = p >> 7;                   // 2..6
        const int r = p & 127;                  // even
        float s, c;
        __sincosf((float)r * (PI_F / 256.0f), &s, &c);
        const float c1 = c * cd - s * sd;
        const float s1 = s * cd + c * sd;
        const float w0 = 0.5f - 0.5f * c,  u0 = 0.5f - 0.5f * c1;
        const float w1 = 0.5f + 0.5f * s,  u1 = 0.5f + 0.5f * s1;
        const float w2 = 0.5f + 0.5f * c,  u2 = 0.5f + 0.5f * c1;
        const float w3 = 0.5f - 0.5f * s,  u3 = 0.5f - 0.5f * s1;
        const int base = ((e * 6 + q) << 8) + (r >> 1);

        const float2 v1 = fb[base - 192];
        const float2 v2 = fb[base - 384];
        float acc0 = w1 * v1.x + w2 * v2.x;
        float acc1 = u1 * v1.y + u2 * v2.y;
        float env0 = w1 * w1 + w2 * w2;
        float env1 = u1 * u1 + u2 * u2;
        if (q <= 5) {
            const float2 v0 = fb[base];
            acc0 = fmaf(w0, v0.x, acc0); env0 = fmaf(w0, w0, env0);
            acc1 = fmaf(u0, v0.y, acc1); env1 = fmaf(u0, u0, env1);
        }
        if (q >= 3) {
            const float2 v3 = fb[base - 576];
            acc0 = fmaf(w3, v3.x, acc0); env0 = fmaf(w3, w3, env0);
            acc1 = fmaf(u3, v3.y, acc1); env1 = fmaf(u3, u3, env1);
        }
        float2 o;
        o.x = __fdividef(acc0, 256.0f * env0);
        o.y = __fdividef(acc1, 256.0f * env1);
        *reinterpret_cast<float2*>(out + ((size_t)b2 * 2 + e) * 600 + 2 * m) = o;
    }
}

extern "C" void kernel_launch(void* const* d_in, const int* in_sizes, int n_in,
                              void* d_out, int out_size) {
    (void)in_sizes; (void)n_in; (void)out_size;
    const float* x = (const float*)d_in[0];
    float* out = (float*)d_out;
    istft_kernel<<<4096, NT>>>(x, out);
}